// round 1
// baseline (speedup 1.0000x reference)
#include <cuda_runtime.h>
#include <cuda_bf16.h>

// ---------------------------------------------------------------------------
// AffinityHead — fp32 implementation with f32x2 packed-FMA GEMM core.
//
// Pipeline (all on default stream, graph-capturable, no allocations):
//   k_tok    : tok = silu(token_features) @ W_token + b_token          [4,128,128]
//   k_S1/k_S0: shifted-window sums of silu(ms_feat_*) (conv-mean trick)
//   k_pconv  : p0/p1 from S-sums x conv weights                        [4,256]
//   k_pf     : pocket MLP + token agg + cat/gate                       [4,128]
//   k_atoms  : atoms = lig_atom @ W_atom + b_atom                      [4,1024,128]
//   k_inter  : per-atom 128x128x128 GEMM H = T @ (diag(a) W_int),
//              lrelu, pe/pg dots, sigmoid-gate, sum over tokens -> atom_e
//   k_final  : segment-sum atom_e by ligand_batch + bias MLP -> out    [4,64]
// ---------------------------------------------------------------------------

typedef unsigned long long ull;

#define FMA2(c, a, b) asm("fma.rn.f32x2 %0, %1, %2, %0;" : "+l"(c) : "l"(a), "l"(b))

__device__ __forceinline__ ull splat2(float f) {
    ull r;
    unsigned u = __float_as_uint(f);
    asm("mov.b64 %0, {%1, %1};" : "=l"(r) : "r"(u));
    return r;
}

__device__ __forceinline__ float silu_f(float v) { return v / (1.f + __expf(-v)); }

// ------------------------- scratch (static, no allocs) ---------------------
__device__ float g_tok[4 * 128 * 128];     // [n][j][h]
__device__ float g_S1[4 * 64 * 27];        // shifted sums for ms_feat_1
__device__ float g_S0[4 * 32 * 27];        // shifted sums for ms_feat_0
__device__ float g_p[4 * 256];             // [n][p0(128) | p1(128)]
__device__ float g_pf[4 * 128];            // gated pocket feature
__device__ float g_atoms[4 * 1024 * 128];  // [n][i][k]
__device__ float g_atom_e[4 * 1024];       // per-atom energies

// ------------------------------ k_tok --------------------------------------
__global__ void k_tok(const float* __restrict__ tf, const float* __restrict__ Wt,
                      const float* __restrict__ bt) {
    int row = blockIdx.x;      // n*128 + j  (512 rows)
    int t = threadIdx.x;       // 128
    __shared__ float s[256];
    const float* x = tf + row * 256;
    for (int c = t; c < 256; c += 128) s[c] = silu_f(x[c]);
    __syncthreads();
    float acc = bt[t];
#pragma unroll 8
    for (int c = 0; c < 256; c++) acc += s[c] * Wt[c * 128 + t];
    g_tok[row * 128 + t] = acc;
}

// ------------------------------ k_S1 ----------------------------------------
// ms_feat_1: [4,64,8,8,8]; 27 shifted sums over the 6^3 valid-output window.
__global__ void k_S1(const float* __restrict__ x) {
    int nc = blockIdx.x;       // 4*64
    int t = threadIdx.x;       // 128
    __shared__ float v[512];
    for (int i = t; i < 512; i += 128) v[i] = silu_f(x[nc * 512 + i]);
    __syncthreads();
    if (t < 27) {
        int kd = t / 9, kh = (t / 3) % 3, kw = t % 3;
        float s = 0.f;
        for (int d = 0; d < 6; d++)
            for (int h = 0; h < 6; h++)
                for (int w = 0; w < 6; w++)
                    s += v[(d + kd) * 64 + (h + kh) * 8 + (w + kw)];
        g_S1[nc * 27 + t] = s;
    }
}

// ------------------------------ k_S0 ----------------------------------------
// ms_feat_0: [4,32,16,16,16]; 27 shifted sums over the 14^3 window.
__global__ void k_S0(const float* __restrict__ x) {
    int nc = blockIdx.x;       // 4*32
    int t = threadIdx.x;       // 256
    __shared__ float v[4096];
    __shared__ float rbuf[8];
    for (int i = t; i < 4096; i += 256) v[i] = silu_f(x[nc * 4096 + i]);
    __syncthreads();
    for (int k = 0; k < 27; k++) {
        int kd = k / 9, kh = (k / 3) % 3, kw = k % 3;
        float s = 0.f;
        for (int p = t; p < 2744; p += 256) {
            int d = p / 196;
            int r = p % 196;
            int hh = r / 14, ww = r % 14;
            s += v[(d + kd) * 256 + (hh + kh) * 16 + (ww + kw)];
        }
        for (int off = 16; off > 0; off >>= 1) s += __shfl_down_sync(0xffffffffu, s, off);
        if ((t & 31) == 0) rbuf[t >> 5] = s;
        __syncthreads();
        if (t == 0) {
            float tot = 0.f;
            for (int w = 0; w < 8; w++) tot += rbuf[w];
            g_S0[nc * 27 + k] = tot;
        }
        __syncthreads();
    }
}

// ------------------------------ k_pconv -------------------------------------
// p0[n,o] = dot(S1[n,:], Wc0[o,:]) / 216 + bc0[o]   (1728 = 64*27)
// p1[n,o] = dot(S0[n,:], Wc1[o,:]) / 2744 + bc1[o]  (864  = 32*27)
__global__ void k_pconv(const float* __restrict__ Wc0, const float* __restrict__ bc0,
                        const float* __restrict__ Wc1, const float* __restrict__ bc1) {
    int n = blockIdx.x, t = threadIdx.x;   // 4 x 128
    __shared__ float s1[1728];
    __shared__ float s0[864];
    for (int i = t; i < 1728; i += 128) s1[i] = g_S1[n * 1728 + i];
    for (int i = t; i < 864; i += 128) s0[i] = g_S0[n * 864 + i];
    __syncthreads();
    float a0 = 0.f;
#pragma unroll 4
    for (int x = 0; x < 1728; x++) a0 += s1[x] * Wc0[t * 1728 + x];
    g_p[n * 256 + t] = a0 * (1.f / 216.f) + bc0[t];
    float a1 = 0.f;
#pragma unroll 4
    for (int x = 0; x < 864; x++) a1 += s0[x] * Wc1[t * 864 + x];
    g_p[n * 256 + 128 + t] = a1 * (1.f / 2744.f) + bc1[t];
}

// ------------------------------ k_pf ----------------------------------------
__global__ void k_pf(const float* __restrict__ Wp, const float* __restrict__ bp,
                     const float* __restrict__ Wcat, const float* __restrict__ bcat,
                     const float* __restrict__ Wgate, const float* __restrict__ bgate) {
    int n = blockIdx.x, t = threadIdx.x;   // 4 x 128
    __shared__ float sp[256];
    __shared__ float pin[384];
    for (int c = t; c < 256; c += 128) sp[c] = silu_f(g_p[n * 256 + c]);
    float ts = 0.f;
    for (int j = 0; j < 128; j++) ts += g_tok[(n * 128 + j) * 128 + t];
    __syncthreads();
    float pk = bp[t];
#pragma unroll 4
    for (int c = 0; c < 256; c++) pk += sp[c] * Wp[c * 128 + t];
    pin[t] = pk;
    pin[128 + t] = ts;
    pin[256 + t] = ts * (1.f / 128.f);
    __syncthreads();
    float c1 = bcat[t], g1 = bgate[t];
#pragma unroll 4
    for (int c = 0; c < 384; c++) {
        float z = pin[c];
        c1 += z * Wcat[c * 128 + t];
        g1 += z * Wgate[c * 128 + t];
    }
    g_pf[n * 128 + t] = c1 / (1.f + __expf(-g1));
}

// ------------------------------ k_atoms -------------------------------------
__global__ void k_atoms(const float* __restrict__ la, const float* __restrict__ Wa,
                        const float* __restrict__ ba) {
    int r0 = blockIdx.x * 8;   // 512 blocks, 8 rows each (4096 rows total)
    int t = threadIdx.x;       // 128
    __shared__ float s[8][64];
    for (int i = t; i < 512; i += 128) s[i >> 6][i & 63] = la[r0 * 64 + i];
    __syncthreads();
    float b = ba[t];
    float acc[8];
#pragma unroll
    for (int r = 0; r < 8; r++) acc[r] = b;
    for (int c = 0; c < 64; c++) {
        float w = Wa[c * 128 + t];
#pragma unroll
        for (int r = 0; r < 8; r++) acc[r] += s[r][c] * w;
    }
#pragma unroll
    for (int r = 0; r < 8; r++) g_atoms[(r0 + r) * 128 + t] = acc[r];
}

// ------------------------------ k_inter -------------------------------------
#define TT_STRIDE 132
#define SM_TT 0
#define SM_WS (128 * TT_STRIDE)          // 16896
#define SM_MS (SM_WS + 16384)            // 33280
#define SM_AV (SM_MS + 16384)            // 49664
#define SM_CV (SM_AV + 128)              // 49792 : wpe(128) | wpg(128) | b_int(128)
#define SM_RED (SM_CV + 384)             // 50176
#define SM_FLOATS (SM_RED + 16)          // 50192
#define SMEM_INTER_BYTES (SM_FLOATS * 4) // 200768 bytes

__global__ void __launch_bounds__(256, 1)
k_inter(const float* __restrict__ Wi, const float* __restrict__ bi,
        const float* __restrict__ wpe, const float* __restrict__ bpe,
        const float* __restrict__ wpg, const float* __restrict__ bpg) {
    extern __shared__ float sm[];
    float* Tt = sm + SM_TT;    // tok transposed [k][j], stride 132
    float* Ws = sm + SM_WS;    // W_int [k][h]
    float* Ms = sm + SM_MS;    // a[k] * W_int[k][h]
    float* av = sm + SM_AV;    // atom vector
    float* cv = sm + SM_CV;    // wpe | wpg | b_int
    float* red = sm + SM_RED;  // 16-way partial sums

    const int t = threadIdx.x;
    const int tx = t & 15, ty = t >> 4;
    const int blk = blockIdx.x;       // 1024 blocks
    const int n = blk >> 8;           // 256 blocks per image
    const int i0 = (blk & 255) << 2;  // 4 atoms per block

    const float* tokn = g_tok + n * 16384;
    for (int idx = t; idx < 16384; idx += 256) {
        int j = idx >> 7, k = idx & 127;
        Tt[k * TT_STRIDE + j] = tokn[idx];
        Ws[idx] = Wi[idx];
    }
    if (t < 128) {
        cv[t] = wpe[t];
        cv[128 + t] = wpg[t];
        cv[256 + t] = bi[t];
    }
    const float bpe0 = bpe[0], bpg0 = bpg[0];

    const int j0 = ty << 2;  // rows j0..j0+3 and 64+j0..64+j0+3
    const int h0 = tx << 2;  // cols h0..h0+3 and 64+h0..64+h0+3

    for (int ai = 0; ai < 4; ai++) {
        const int i = i0 + ai;
        __syncthreads();
        if (t < 128) av[t] = g_atoms[(n * 1024 + i) * 128 + t];
        __syncthreads();
        for (int idx = t; idx < 16384; idx += 256) Ms[idx] = av[idx >> 7] * Ws[idx];
        __syncthreads();

        ull acc[4][8];
#pragma unroll
        for (int y = 0; y < 4; y++)
#pragma unroll
            for (int x = 0; x < 8; x++) acc[y][x] = 0ull;

#pragma unroll 4
        for (int k = 0; k < 128; k++) {
            const float* tr = Tt + k * TT_STRIDE;
            const float* mr = Ms + (k << 7);
            ull a0 = *(const ull*)(tr + j0);
            ull a1 = *(const ull*)(tr + j0 + 2);
            ull a2 = *(const ull*)(tr + 64 + j0);
            ull a3 = *(const ull*)(tr + 64 + j0 + 2);
            float4 b0 = *(const float4*)(mr + h0);
            float4 b1 = *(const float4*)(mr + 64 + h0);
            ull bb[8];
            bb[0] = splat2(b0.x); bb[1] = splat2(b0.y);
            bb[2] = splat2(b0.z); bb[3] = splat2(b0.w);
            bb[4] = splat2(b1.x); bb[5] = splat2(b1.y);
            bb[6] = splat2(b1.z); bb[7] = splat2(b1.w);
#pragma unroll
            for (int x = 0; x < 8; x++) {
                FMA2(acc[0][x], a0, bb[x]);
                FMA2(acc[1][x], a1, bb[x]);
                FMA2(acc[2][x], a2, bb[x]);
                FMA2(acc[3][x], a3, bb[x]);
            }
        }

        // Epilogue: h -> lrelu -> (pe, pg) dots per token row
        float pe_p[8], pg_p[8];
#pragma unroll
        for (int r = 0; r < 8; r++) { pe_p[r] = 0.f; pg_p[r] = 0.f; }
#pragma unroll
        for (int x = 0; x < 8; x++) {
            const int h = (x < 4) ? (h0 + x) : (64 + h0 + x - 4);
            const float wpeh = cv[h];
            const float wpgh = cv[128 + h];
            const float bih = cv[256 + h];
#pragma unroll
            for (int yp = 0; yp < 4; yp++) {
                unsigned lo_u, hi_u;
                asm("mov.b64 {%0, %1}, %2;" : "=r"(lo_u), "=r"(hi_u) : "l"(acc[yp][x]));
                float v0 = __uint_as_float(lo_u) + bih;
                float v1 = __uint_as_float(hi_u) + bih;
                v0 = (v0 > 0.f) ? v0 : 0.01f * v0;
                v1 = (v1 > 0.f) ? v1 : 0.01f * v1;
                pe_p[2 * yp] += v0 * wpeh;
                pe_p[2 * yp + 1] += v1 * wpeh;
                pg_p[2 * yp] += v0 * wpgh;
                pg_p[2 * yp + 1] += v1 * wpgh;
            }
        }
        // reduce across the 16 tx threads (half-warp butterflies)
#pragma unroll
        for (int r = 0; r < 8; r++) {
#pragma unroll
            for (int off = 8; off > 0; off >>= 1) {
                pe_p[r] += __shfl_xor_sync(0xffffffffu, pe_p[r], off);
                pg_p[r] += __shfl_xor_sync(0xffffffffu, pg_p[r], off);
            }
        }
        if (tx == 0) {
            float loc = 0.f;
#pragma unroll
            for (int r = 0; r < 8; r++) {
                float spe = pe_p[r] + bpe0;
                float spg = pg_p[r] + bpg0;
                loc += spe / (1.f + __expf(-spg));
            }
            red[ty] = loc;
        }
        __syncthreads();
        if (t == 0) {
            float s = 0.f;
#pragma unroll
            for (int w = 0; w < 16; w++) s += red[w];
            g_atom_e[n * 1024 + i] = s;
        }
    }
}

// ------------------------------ k_final -------------------------------------
__global__ void k_final(const float* __restrict__ lgr, const int* __restrict__ lb,
                        const float* __restrict__ Wgr, const float* __restrict__ bgr,
                        const float* __restrict__ Wb1, const float* __restrict__ bb1,
                        const float* __restrict__ Wb2, const float* __restrict__ bb2,
                        float* __restrict__ out) {
    int n = blockIdx.x >> 6, g = blockIdx.x & 63, t = threadIdx.x;  // 256 x 128
    __shared__ float z[256];
    __shared__ float lg[64];
    __shared__ float red[8];
    if (t < 64) lg[t] = lgr[(n * 64 + g) * 64 + t];
    z[t] = g_pf[n * 128 + t];
    __syncthreads();
    float gf = bgr[t];
#pragma unroll 4
    for (int c = 0; c < 64; c++) gf += lg[c] * Wgr[c * 128 + t];
    z[128 + t] = gf;
    __syncthreads();
    float h = bb1[t];
#pragma unroll 4
    for (int c = 0; c < 256; c++) h += z[c] * Wb1[c * 128 + t];
    h = (h > 0.f) ? h : 0.01f * h;
    float part = h * Wb2[t];
    float seg = 0.f;
    for (int a = t; a < 1024; a += 128) {
        if (lb[a] == g) seg += g_atom_e[n * 1024 + a];
    }
#pragma unroll
    for (int off = 16; off > 0; off >>= 1) {
        part += __shfl_down_sync(0xffffffffu, part, off);
        seg += __shfl_down_sync(0xffffffffu, seg, off);
    }
    int wid = t >> 5;
    if ((t & 31) == 0) {
        red[wid] = part;
        red[4 + wid] = seg;
    }
    __syncthreads();
    if (t == 0) {
        float bias = red[0] + red[1] + red[2] + red[3] + bb2[0];
        float segs = red[4] + red[5] + red[6] + red[7];
        out[n * 64 + g] = segs + bias;
    }
}

// ------------------------------ launch --------------------------------------
extern "C" void kernel_launch(void* const* d_in, const int* in_sizes, int n_in,
                              void* d_out, int out_size) {
    const float* ms0 = (const float*)d_in[0];
    const float* ms1 = (const float*)d_in[1];
    const float* tf = (const float*)d_in[2];
    const float* lat = (const float*)d_in[3];
    const float* lgr = (const float*)d_in[4];
    const int* lb = (const int*)d_in[5];
    const float* Wt = (const float*)d_in[6];
    const float* bt = (const float*)d_in[7];
    const float* Wc0 = (const float*)d_in[8];
    const float* bc0 = (const float*)d_in[9];
    const float* Wc1 = (const float*)d_in[10];
    const float* bc1 = (const float*)d_in[11];
    const float* Wp = (const float*)d_in[12];
    const float* bp = (const float*)d_in[13];
    const float* Wcat = (const float*)d_in[14];
    const float* bcat = (const float*)d_in[15];
    const float* Wgate = (const float*)d_in[16];
    const float* bgate = (const float*)d_in[17];
    const float* Wa = (const float*)d_in[18];
    const float* ba = (const float*)d_in[19];
    const float* Wgr = (const float*)d_in[20];
    const float* bgr = (const float*)d_in[21];
    const float* Wb1 = (const float*)d_in[22];
    const float* bb1 = (const float*)d_in[23];
    const float* Wb2 = (const float*)d_in[24];
    const float* bb2 = (const float*)d_in[25];
    const float* Wi = (const float*)d_in[26];
    const float* bi = (const float*)d_in[27];
    const float* wpe = (const float*)d_in[28];
    const float* bpe = (const float*)d_in[29];
    const float* wpg = (const float*)d_in[30];
    const float* bpg = (const float*)d_in[31];
    float* out = (float*)d_out;

    k_tok<<<512, 128>>>(tf, Wt, bt);
    k_S1<<<256, 128>>>(ms1);
    k_S0<<<128, 256>>>(ms0);
    k_pconv<<<4, 128>>>(Wc0, bc0, Wc1, bc1);
    k_pf<<<4, 128>>>(Wp, bp, Wcat, bcat, Wgate, bgate);
    k_atoms<<<512, 128>>>(lat, Wa, ba);

    cudaFuncSetAttribute(k_inter, cudaFuncAttributeMaxDynamicSharedMemorySize,
                         SMEM_INTER_BYTES);
    k_inter<<<1024, 256, SMEM_INTER_BYTES>>>(Wi, bi, wpe, bpe, wpg, bpg);

    k_final<<<256, 128>>>(lgr, lb, Wgr, bgr, Wb1, bb1, Wb2, bb2, out);
}

// round 3
// speedup vs baseline: 2.4711x; 2.4711x over previous
#include <cuda_runtime.h>
#include <cuda_bf16.h>
#include <cstdint>

// ---------------------------------------------------------------------------
// AffinityHead — mma.sync (bf16 x3 split) tensor-core GEMM core.
//   (tcgen05 is PTX-gated to sm_103a targets; harness PTX pass is sm_103,
//    so we use the legacy mma.sync/ldmatrix path: register accumulators.)
// ---------------------------------------------------------------------------

__device__ __forceinline__ float silu_f(float v) { return v / (1.f + __expf(-v)); }

// ------------------------- scratch (static, no allocs) ---------------------
__device__ float g_tok[4 * 128 * 128];     // [n][j][h]
__device__ float g_S1[4 * 64 * 27];
__device__ float g_S0[4 * 32 * 27];
__device__ float g_p[4 * 256];
__device__ float g_pf[4 * 128];
__device__ float g_atoms[4 * 1024 * 128];  // [n][i][k]
__device__ float g_atom_e[4 * 1024];

// ------------------------------ PTX helpers --------------------------------
__device__ __forceinline__ uint32_t smem_to_u32(const void* p) {
    uint32_t a;
    asm("{ .reg .u64 t; cvta.to.shared.u64 t, %1; cvt.u32.u64 %0, t; }" : "=r"(a) : "l"(p));
    return a;
}

__device__ __forceinline__ void ldsm_x4(uint32_t* r, uint32_t addr) {
    asm volatile("ldmatrix.sync.aligned.m8n8.x4.shared.b16 {%0,%1,%2,%3}, [%4];"
                 : "=r"(r[0]), "=r"(r[1]), "=r"(r[2]), "=r"(r[3]) : "r"(addr));
}

__device__ __forceinline__ void mma_bf16(float* d, const uint32_t* a, const uint32_t* b) {
    asm volatile(
        "mma.sync.aligned.m16n8k16.row.col.f32.bf16.bf16.f32 "
        "{%0,%1,%2,%3}, {%4,%5,%6,%7}, {%8,%9}, {%0,%1,%2,%3};"
        : "+f"(d[0]), "+f"(d[1]), "+f"(d[2]), "+f"(d[3])
        : "r"(a[0]), "r"(a[1]), "r"(a[2]), "r"(a[3]), "r"(b[0]), "r"(b[1]));
}

// ------------------------------ k_tok --------------------------------------
__global__ void k_tok(const float* __restrict__ tf, const float* __restrict__ Wt,
                      const float* __restrict__ bt) {
    int row = blockIdx.x;
    int t = threadIdx.x;
    __shared__ float s[256];
    const float* x = tf + row * 256;
    for (int c = t; c < 256; c += 128) s[c] = silu_f(x[c]);
    __syncthreads();
    float acc = bt[t];
#pragma unroll 8
    for (int c = 0; c < 256; c++) acc += s[c] * Wt[c * 128 + t];
    g_tok[row * 128 + t] = acc;
}

// ------------------------------ k_S1 ----------------------------------------
__global__ void k_S1(const float* __restrict__ x) {
    int nc = blockIdx.x;
    int t = threadIdx.x;
    __shared__ float v[512];
    for (int i = t; i < 512; i += 128) v[i] = silu_f(x[nc * 512 + i]);
    __syncthreads();
    if (t < 27) {
        int kd = t / 9, kh = (t / 3) % 3, kw = t % 3;
        float s = 0.f;
        for (int d = 0; d < 6; d++)
            for (int h = 0; h < 6; h++)
                for (int w = 0; w < 6; w++)
                    s += v[(d + kd) * 64 + (h + kh) * 8 + (w + kw)];
        g_S1[nc * 27 + t] = s;
    }
}

// ------------------------------ k_S0 ----------------------------------------
__global__ void k_S0(const float* __restrict__ x) {
    int nc = blockIdx.x;
    int t = threadIdx.x;
    __shared__ float v[4096];
    __shared__ float rbuf[8];
    for (int i = t; i < 4096; i += 256) v[i] = silu_f(x[nc * 4096 + i]);
    __syncthreads();
    for (int k = 0; k < 27; k++) {
        int kd = k / 9, kh = (k / 3) % 3, kw = k % 3;
        float s = 0.f;
        for (int p = t; p < 2744; p += 256) {
            int d = p / 196;
            int r = p % 196;
            int hh = r / 14, ww = r % 14;
            s += v[(d + kd) * 256 + (hh + kh) * 16 + (ww + kw)];
        }
        for (int off = 16; off > 0; off >>= 1) s += __shfl_down_sync(0xffffffffu, s, off);
        if ((t & 31) == 0) rbuf[t >> 5] = s;
        __syncthreads();
        if (t == 0) {
            float tot = 0.f;
            for (int w = 0; w < 8; w++) tot += rbuf[w];
            g_S0[nc * 27 + k] = tot;
        }
        __syncthreads();
    }
}

// ------------------------------ k_pconv (warp-per-output) -------------------
__global__ void k_pconv(const float* __restrict__ Wc0, const float* __restrict__ bc0,
                        const float* __restrict__ Wc1, const float* __restrict__ bc1) {
    int b = blockIdx.x, t = threadIdx.x;   // 64 blocks x 256 threads
    int n = b >> 4, og = b & 15;
    __shared__ float s1[1728];
    __shared__ float s0[864];
    for (int i = t; i < 1728; i += 256) s1[i] = g_S1[n * 1728 + i];
    for (int i = t; i < 864; i += 256) s0[i] = g_S0[n * 864 + i];
    __syncthreads();
    int w = t >> 5, lane = t & 31;
    int o = og * 8 + w;
    float a0 = 0.f;
    for (int x = lane; x < 1728; x += 32) a0 += s1[x] * Wc0[o * 1728 + x];
    float a1 = 0.f;
    for (int x = lane; x < 864; x += 32) a1 += s0[x] * Wc1[o * 864 + x];
#pragma unroll
    for (int off = 16; off > 0; off >>= 1) {
        a0 += __shfl_down_sync(0xffffffffu, a0, off);
        a1 += __shfl_down_sync(0xffffffffu, a1, off);
    }
    if (lane == 0) {
        g_p[n * 256 + o] = a0 * (1.f / 216.f) + bc0[o];
        g_p[n * 256 + 128 + o] = a1 * (1.f / 2744.f) + bc1[o];
    }
}

// ------------------------------ k_pf ----------------------------------------
__global__ void k_pf(const float* __restrict__ Wp, const float* __restrict__ bp,
                     const float* __restrict__ Wcat, const float* __restrict__ bcat,
                     const float* __restrict__ Wgate, const float* __restrict__ bgate) {
    int n = blockIdx.x, t = threadIdx.x;
    __shared__ float sp[256];
    __shared__ float pin[384];
    for (int c = t; c < 256; c += 128) sp[c] = silu_f(g_p[n * 256 + c]);
    float ts = 0.f;
    for (int j = 0; j < 128; j++) ts += g_tok[(n * 128 + j) * 128 + t];
    __syncthreads();
    float pk = bp[t];
#pragma unroll 4
    for (int c = 0; c < 256; c++) pk += sp[c] * Wp[c * 128 + t];
    pin[t] = pk;
    pin[128 + t] = ts;
    pin[256 + t] = ts * (1.f / 128.f);
    __syncthreads();
    float c1 = bcat[t], g1 = bgate[t];
#pragma unroll 4
    for (int c = 0; c < 384; c++) {
        float z = pin[c];
        c1 += z * Wcat[c * 128 + t];
        g1 += z * Wgate[c * 128 + t];
    }
    g_pf[n * 128 + t] = c1 / (1.f + __expf(-g1));
}

// ------------------------------ k_atoms -------------------------------------
__global__ void k_atoms(const float* __restrict__ la, const float* __restrict__ Wa,
                        const float* __restrict__ ba) {
    int r0 = blockIdx.x * 8;
    int t = threadIdx.x;
    __shared__ float s[8][64];
    for (int i = t; i < 512; i += 128) s[i >> 6][i & 63] = la[r0 * 64 + i];
    __syncthreads();
    float b = ba[t];
    float acc[8];
#pragma unroll
    for (int r = 0; r < 8; r++) acc[r] = b;
    for (int c = 0; c < 64; c++) {
        float w = Wa[c * 128 + t];
#pragma unroll
        for (int r = 0; r < 8; r++) acc[r] += s[r][c] * w;
    }
#pragma unroll
    for (int r = 0; r < 8; r++) g_atoms[(r0 + r) * 128 + t] = acc[r];
}

// ------------------------------ k_inter (mma.sync) --------------------------
// Byte offsets into dynamic smem. bf16 planes use row stride 136 halves (272B)
// -> conflict-free ldmatrix; WfT uses stride 130 floats (520B) -> conflict-free
// 8B-aligned float2 access.
#define STH 0                 // tok hi  [128][136] bf16 : 34816
#define STL 34816             // tok lo
#define SMH 69632             // M hi
#define SML 104448            // M lo
#define SWT 139264            // W^T fp32 [128][130] : 66560
#define SAV 205824            // atom vec : 512
#define SCV 206336            // wpe|wpg|bi : 1536
#define SPE 207872            // pe/pg bufs [2][2][128] : 4096
#define SRED 211968           // 16
#define SMEM_TC_BYTES 212096

__global__ void __launch_bounds__(256, 1)
k_inter(const float* __restrict__ Wi, const float* __restrict__ bi,
        const float* __restrict__ wpe, const float* __restrict__ bpe,
        const float* __restrict__ wpg, const float* __restrict__ bpg) {
    extern __shared__ char smc[];
    const uint32_t sb = smem_to_u32(smc);
    float* WfT = (float*)(smc + SWT);
    float* av = (float*)(smc + SAV);
    float* cv = (float*)(smc + SCV);
    float* peb = (float*)(smc + SPE);        // [2][128]
    float* pgb = peb + 256;                  // [2][128]
    float* red = (float*)(smc + SRED);

    const int t = threadIdx.x;
    const int wid = t >> 5;
    const int lane = t & 31;

    const int n = blockIdx.x / 37;
    const int grp = blockIdx.x % 37;
    const int i0 = grp * 28;
    const int cnt = min(28, 1024 - i0);

    // ---- load W^T (fp32) and constants ----
    const float* tokn = g_tok + n * 16384;
    for (int idx = t; idx < 16384; idx += 256) {
        int k = idx >> 7, h = idx & 127;
        WfT[h * 130 + k] = Wi[idx];
    }
    if (t < 128) {
        cv[t] = wpe[t];
        cv[128 + t] = wpg[t];
        cv[256 + t] = bi[t];
    }
    const float bpe0 = bpe[0], bpg0 = bpg[0];

    // ---- build tok hi/lo planes (A operand), once per block ----
    for (int p = t; p < 8192; p += 256) {
        int j = p >> 6, k2 = p & 63;
        float2 v = *(const float2*)(tokn + j * 128 + 2 * k2);
        __nv_bfloat162 hi = __float22bfloat162_rn(make_float2(v.x, v.y));
        float r0 = v.x - __low2float(hi);
        float r1 = v.y - __high2float(hi);
        __nv_bfloat162 lo = __float22bfloat162_rn(make_float2(r0, r1));
        uint32_t off = (uint32_t)(j * 272 + 4 * k2);
        *(__nv_bfloat162*)(smc + STH + off) = hi;
        *(__nv_bfloat162*)(smc + STL + off) = lo;
    }
    __syncthreads();

    // ---- per-warp tile / ldmatrix lane addresses ----
    const int j0 = (wid & 3) * 32;   // 32 token rows per warp
    const int h0 = (wid >> 2) * 64;  // 64 h cols per warp-half

    const int aRow = lane & 15;
    const int aK = (lane >> 4) << 3;
    const uint32_t aOffH = sb + STH + (uint32_t)((j0 + aRow) * 272 + aK * 2);
    const uint32_t aOffL = sb + STL + (uint32_t)((j0 + aRow) * 272 + aK * 2);
    const int bRow = ((lane >> 4) << 3) + (lane & 7);
    const int bK = ((lane >> 3) & 1) << 3;
    const uint32_t bOffH = sb + SMH + (uint32_t)((h0 + bRow) * 272 + bK * 2);
    const uint32_t bOffL = sb + SML + (uint32_t)((h0 + bRow) * 272 + bK * 2);

    for (int a = 0; a < cnt; a++) {
        if (t < 128) av[t] = g_atoms[(n * 1024 + i0 + a) * 128 + t];
        __syncthreads();

        // ---- build M = diag(av) * W as bf16 hi/lo, [h][k] layout ----
        for (int p = t; p < 8192; p += 256) {
            int h = p >> 6, k2 = p & 63;
            float2 w = *(const float2*)(WfT + h * 130 + 2 * k2);
            float2 a2 = *(const float2*)(av + 2 * k2);
            float v0 = a2.x * w.x, v1 = a2.y * w.y;
            __nv_bfloat162 hi = __float22bfloat162_rn(make_float2(v0, v1));
            float r0 = v0 - __low2float(hi);
            float r1 = v1 - __high2float(hi);
            __nv_bfloat162 lo = __float22bfloat162_rn(make_float2(r0, r1));
            uint32_t off = (uint32_t)(h * 272 + 4 * k2);
            *(__nv_bfloat162*)(smc + SMH + off) = hi;
            *(__nv_bfloat162*)(smc + SML + off) = lo;
        }
        __syncthreads();

        // ---- mma mainloop: C[32x64] = sum_k T * M, 3 split terms ----
        float acc[2][8][4];
#pragma unroll
        for (int mt = 0; mt < 2; mt++)
#pragma unroll
            for (int nt = 0; nt < 8; nt++)
#pragma unroll
                for (int e = 0; e < 4; e++) acc[mt][nt][e] = 0.f;

#pragma unroll
        for (int ks = 0; ks < 8; ks++) {
            const uint32_t ko = (uint32_t)(ks * 32);
            uint32_t aH[2][4], aL[2][4], bH[4][4], bL[4][4];
            ldsm_x4(aH[0], aOffH + ko);
            ldsm_x4(aH[1], aOffH + 4352 + ko);
            ldsm_x4(aL[0], aOffL + ko);
            ldsm_x4(aL[1], aOffL + 4352 + ko);
#pragma unroll
            for (int ng = 0; ng < 4; ng++) {
                ldsm_x4(bH[ng], bOffH + (uint32_t)(ng * 4352) + ko);
                ldsm_x4(bL[ng], bOffL + (uint32_t)(ng * 4352) + ko);
            }
#pragma unroll
            for (int mt = 0; mt < 2; mt++) {
#pragma unroll
                for (int ng = 0; ng < 4; ng++) {
                    mma_bf16(acc[mt][2 * ng], aH[mt], bH[ng]);
                    mma_bf16(acc[mt][2 * ng + 1], aH[mt], bH[ng] + 2);
                    mma_bf16(acc[mt][2 * ng], aH[mt], bL[ng]);
                    mma_bf16(acc[mt][2 * ng + 1], aH[mt], bL[ng] + 2);
                    mma_bf16(acc[mt][2 * ng], aL[mt], bH[ng]);
                    mma_bf16(acc[mt][2 * ng + 1], aL[mt], bH[ng] + 2);
                }
            }
        }

        // ---- epilogue: lrelu + pe/pg dots, per-row partials ----
        float pe[4] = {0.f, 0.f, 0.f, 0.f}, pg[4] = {0.f, 0.f, 0.f, 0.f};
#pragma unroll
        for (int nt = 0; nt < 8; nt++) {
#pragma unroll
            for (int c = 0; c < 2; c++) {
                const int h = h0 + 8 * nt + 2 * (lane & 3) + c;
                const float wpeh = cv[h];
                const float wpgh = cv[128 + h];
                const float bih = cv[256 + h];
#pragma unroll
                for (int mt = 0; mt < 2; mt++) {
#pragma unroll
                    for (int hf = 0; hf < 2; hf++) {
                        float v = acc[mt][nt][hf * 2 + c] + bih;
                        v = (v > 0.f) ? v : 0.01f * v;
                        pe[mt * 2 + hf] += v * wpeh;
                        pg[mt * 2 + hf] += v * wpgh;
                    }
                }
            }
        }
        // reduce over the 4 lanes sharing a row (lane&3)
#pragma unroll
        for (int rs = 0; rs < 4; rs++) {
#pragma unroll
            for (int off = 1; off < 4; off <<= 1) {
                pe[rs] += __shfl_xor_sync(0xffffffffu, pe[rs], off);
                pg[rs] += __shfl_xor_sync(0xffffffffu, pg[rs], off);
            }
        }
        if ((lane & 3) == 0) {
            const int wx = wid >> 2;
#pragma unroll
            for (int mt = 0; mt < 2; mt++)
#pragma unroll
                for (int hf = 0; hf < 2; hf++) {
                    int j = j0 + 16 * mt + 8 * hf + (lane >> 2);
                    peb[wx * 128 + j] = pe[mt * 2 + hf];
                    pgb[wx * 128 + j] = pg[mt * 2 + hf];
                }
        }
        __syncthreads();

        // ---- final reduce over tokens ----
        if (t < 128) {
            float spe = peb[t] + peb[128 + t] + bpe0;
            float spg = pgb[t] + pgb[128 + t] + bpg0;
            float sj = spe / (1.f + __expf(-spg));
#pragma unroll
            for (int off = 16; off > 0; off >>= 1)
                sj += __shfl_xor_sync(0xffffffffu, sj, off);
            if (lane == 0) red[wid] = sj;
        }
        __syncthreads();
        if (t == 0) g_atom_e[n * 1024 + i0 + a] = red[0] + red[1] + red[2] + red[3];
        __syncthreads();
    }
}

// ------------------------------ k_final -------------------------------------
__global__ void k_final(const float* __restrict__ lgr, const int* __restrict__ lb,
                        const float* __restrict__ Wgr, const float* __restrict__ bgr,
                        const float* __restrict__ Wb1, const float* __restrict__ bb1,
                        const float* __restrict__ Wb2, const float* __restrict__ bb2,
                        float* __restrict__ out) {
    int n = blockIdx.x >> 6, g = blockIdx.x & 63, t = threadIdx.x;
    __shared__ float z[256];
    __shared__ float lg[64];
    __shared__ float red[8];
    if (t < 64) lg[t] = lgr[(n * 64 + g) * 64 + t];
    z[t] = g_pf[n * 128 + t];
    __syncthreads();
    float gf = bgr[t];
#pragma unroll 4
    for (int c = 0; c < 64; c++) gf += lg[c] * Wgr[c * 128 + t];
    z[128 + t] = gf;
    __syncthreads();
    float h = bb1[t];
#pragma unroll 4
    for (int c = 0; c < 256; c++) h += z[c] * Wb1[c * 128 + t];
    h = (h > 0.f) ? h : 0.01f * h;
    float part = h * Wb2[t];
    float seg = 0.f;
    for (int a = t; a < 1024; a += 128) {
        if (lb[a] == g) seg += g_atom_e[n * 1024 + a];
    }
#pragma unroll
    for (int off = 16; off > 0; off >>= 1) {
        part += __shfl_down_sync(0xffffffffu, part, off);
        seg += __shfl_down_sync(0xffffffffu, seg, off);
    }
    int wid = t >> 5;
    if ((t & 31) == 0) {
        red[wid] = part;
        red[4 + wid] = seg;
    }
    __syncthreads();
    if (t == 0) {
        float bias = red[0] + red[1] + red[2] + red[3] + bb2[0];
        float segs = red[4] + red[5] + red[6] + red[7];
        out[n * 64 + g] = segs + bias;
    }
}

// ------------------------------ launch --------------------------------------
extern "C" void kernel_launch(void* const* d_in, const int* in_sizes, int n_in,
                              void* d_out, int out_size) {
    const float* ms0 = (const float*)d_in[0];
    const float* ms1 = (const float*)d_in[1];
    const float* tf = (const float*)d_in[2];
    const float* lat = (const float*)d_in[3];
    const float* lgr = (const float*)d_in[4];
    const int* lb = (const int*)d_in[5];
    const float* Wt = (const float*)d_in[6];
    const float* bt = (const float*)d_in[7];
    const float* Wc0 = (const float*)d_in[8];
    const float* bc0 = (const float*)d_in[9];
    const float* Wc1 = (const float*)d_in[10];
    const float* bc1 = (const float*)d_in[11];
    const float* Wp = (const float*)d_in[12];
    const float* bp = (const float*)d_in[13];
    const float* Wcat = (const float*)d_in[14];
    const float* bcat = (const float*)d_in[15];
    const float* Wgate = (const float*)d_in[16];
    const float* bgate = (const float*)d_in[17];
    const float* Wa = (const float*)d_in[18];
    const float* ba = (const float*)d_in[19];
    const float* Wgr = (const float*)d_in[20];
    const float* bgr = (const float*)d_in[21];
    const float* Wb1 = (const float*)d_in[22];
    const float* bb1 = (const float*)d_in[23];
    const float* Wb2 = (const float*)d_in[24];
    const float* bb2 = (const float*)d_in[25];
    const float* Wi = (const float*)d_in[26];
    const float* bi = (const float*)d_in[27];
    const float* wpe = (const float*)d_in[28];
    const float* bpe = (const float*)d_in[29];
    const float* wpg = (const float*)d_in[30];
    const float* bpg = (const float*)d_in[31];
    float* out = (float*)d_out;

    k_tok<<<512, 128>>>(tf, Wt, bt);
    k_S1<<<256, 128>>>(ms1);
    k_S0<<<128, 256>>>(ms0);
    k_pconv<<<64, 256>>>(Wc0, bc0, Wc1, bc1);
    k_pf<<<4, 128>>>(Wp, bp, Wcat, bcat, Wgate, bgate);
    k_atoms<<<512, 128>>>(lat, Wa, ba);

    cudaFuncSetAttribute(k_inter, cudaFuncAttributeMaxDynamicSharedMemorySize,
                         SMEM_TC_BYTES);
    k_inter<<<148, 256, SMEM_TC_BYTES>>>(Wi, bi, wpe, bpe, wpg, bpg);

    k_final<<<256, 128>>>(lgr, lb, Wgr, bgr, Wb1, bb1, Wb2, bb2, out);
}